// round 13
// baseline (speedup 1.0000x reference)
#include <cuda_runtime.h>
#include <cuda_fp16.h>
#include <math.h>

#define N_ATOMS 50000
#define N_EDGES 800000
#define TBL 16384
#define DMAXF 14.0f
#define LN2F 0.6931471805599453f

// ---------------- device scratch ----------------
__device__ float    g_h   [N_ATOMS * 128];
__device__ __half   g_hf  [N_ATOMS * 128];
__device__ __half   g_aggh[N_ATOMS * 128];
__device__ float    g_d   [N_EDGES];
__device__ unsigned g_metap[N_EDGES];        // src (17b) | table-index (14b) << 17
__device__ int      g_counts[N_ATOMS];
__device__ int      g_start [N_ATOMS];
__device__ int      g_cursor[N_ATOMS];
__device__ __half   g_table[3 * TBL * 128];
__device__ __half   g_whT  [13 * 128 * 128]; // [n][k]: 0-2 ow1, 3-5 ow2, 6-8 afw, 9-11 fw2, 12 w1pad
__device__ __half   g_w1T  [3 * 128 * 32];   // fw1 transposed [n=128][k=32]
__device__ __half   g_embedF[128 * 128];     // embed @ afw0 + afb0 (100 rows used)
__device__ float    g_b1pad[128];
__device__ float    g_aw2pad[128];

__device__ __forceinline__ float sspf(float x) {
    return fmaxf(x, 0.0f) + log1pf(expf(-fabsf(x))) - LN2F;
}

__device__ __forceinline__ void mma_f16(float* d, const unsigned* a, const unsigned* b) {
    asm volatile(
        "mma.sync.aligned.m16n8k16.row.col.f32.f16.f16.f32 "
        "{%0,%1,%2,%3}, {%4,%5,%6,%7}, {%8,%9}, {%0,%1,%2,%3};\n"
        : "+f"(d[0]), "+f"(d[1]), "+f"(d[2]), "+f"(d[3])
        : "r"(a[0]), "r"(a[1]), "r"(a[2]), "r"(a[3]), "r"(b[0]), "r"(b[1]));
}

// ---------------- init ----------------
__global__ void k_init(const int* __restrict__ r, const float* __restrict__ embed,
                       float* __restrict__ out, int out_size) {
    int idx = blockIdx.x * blockDim.x + threadIdx.x;
    if (idx < N_ATOMS * 32) {
        int atom = idx >> 5, j = idx & 31;
        ((float4*)g_h)[atom * 32 + j] = ((const float4*)embed)[(size_t)r[atom] * 32 + j];
    }
    if (idx < N_ATOMS) g_counts[idx] = 0;
    if (idx < out_size) out[idx] = 0.0f;
}

// ---------------- edges ----------------
__global__ void k_edges(const int* __restrict__ a, const float* __restrict__ xyz) {
    int e = blockIdx.x * blockDim.x + threadIdx.x;
    if (e >= N_EDGES) return;
    int d0 = a[2 * e], s0 = a[2 * e + 1];
    float dx = xyz[3 * d0 + 0] - xyz[3 * s0 + 0];
    float dy = xyz[3 * d0 + 1] - xyz[3 * s0 + 1];
    float dz = xyz[3 * d0 + 2] - xyz[3 * s0 + 2];
    g_d[e] = sqrtf(dx * dx + dy * dy + dz * dz + 1e-12f);
    atomicAdd(&g_counts[d0], 1);
}

// ---------------- exclusive scan ----------------
__global__ __launch_bounds__(1024) void k_scan() {
    __shared__ int wsum[32];
    __shared__ int carry;
    __shared__ int tot;
    int t = threadIdx.x, lane = t & 31, w = t >> 5;
    if (t == 0) carry = 0;
    __syncthreads();
    for (int base = 0; base < N_ATOMS; base += 1024) {
        int i = base + t;
        int v = (i < N_ATOMS) ? g_counts[i] : 0;
        int incl = v;
        #pragma unroll
        for (int off = 1; off < 32; off <<= 1) {
            int x = __shfl_up_sync(0xffffffffu, incl, off);
            if (lane >= off) incl += x;
        }
        if (lane == 31) wsum[w] = incl;
        __syncthreads();
        if (w == 0) {
            int s = wsum[lane];
            int si = s;
            #pragma unroll
            for (int off = 1; off < 32; off <<= 1) {
                int x = __shfl_up_sync(0xffffffffu, si, off);
                if (lane >= off) si += x;
            }
            wsum[lane] = si - s;
            if (lane == 31) tot = si;
        }
        __syncthreads();
        int excl = carry + wsum[w] + incl - v;
        if (i < N_ATOMS) { g_start[i] = excl; g_cursor[i] = excl; }
        __syncthreads();
        if (t == 0) carry += tot;
        __syncthreads();
    }
}

// ---------------- scatter: pack (src | i0<<17) ----------------
__global__ void k_scatter(const int* __restrict__ a) {
    int e = blockIdx.x * blockDim.x + threadIdx.x;
    if (e >= N_EDGES) return;
    int d0 = a[2 * e];
    int pos = atomicAdd(&g_cursor[d0], 1);
    float d = g_d[e];
    float u = d * ((float)(TBL - 1) / DMAXF);
    int i0 = (int)(u + 0.5f);
    i0 = min(i0, TBL - 1);
    g_metap[pos] = (unsigned)a[2 * e + 1] | ((unsigned)i0 << 17);
}

// ---------------- weight transpose+convert: fp32 [k][n] -> half [n][k] ----------------
__global__ void k_prep(const float* __restrict__ ow1, const float* __restrict__ ow2,
                       const float* __restrict__ afw, const float* __restrict__ fw2) {
    __shared__ float t[32][33];
    int mat = blockIdx.z;
    const float* src = (mat < 3) ? ow1 + (size_t)mat * 16384
                     : (mat < 6) ? ow2 + (size_t)(mat - 3) * 16384
                     : (mat < 9) ? afw + (size_t)(mat - 6) * 16384
                                 : fw2 + (size_t)(mat - 9) * 16384;
    __half* dst = g_whT + (size_t)mat * 16384;
    int k0 = blockIdx.y * 32, n0 = blockIdx.x * 32;
    int tx = threadIdx.x, ty = threadIdx.y;   // (32, 8)
    #pragma unroll
    for (int q = 0; q < 4; q++)
        t[ty + q * 8][tx] = src[(size_t)(k0 + ty + q * 8) * 128 + n0 + tx];
    __syncthreads();
    #pragma unroll
    for (int q = 0; q < 4; q++)
        dst[(size_t)(n0 + ty + q * 8) * 128 + k0 + tx] = __float2half_rn(t[tx][ty + q * 8]);
}

// ---------------- small prep: fw1 transpose + readout pads (merged) ----------------
__global__ void k_prepsmall(const float* __restrict__ fw1, const float* __restrict__ aw1,
                            const float* __restrict__ ab1, const float* __restrict__ aw2) {
    int i = blockIdx.x * 256 + threadIdx.x;
    if (i < 3 * 128 * 32) {
        int L = i >> 12, rest = i & 4095, n = rest >> 5, k = rest & 31;
        g_w1T[i] = __float2half_rn(fw1[L * 4096 + k * 128 + n]);
    }
    int j = i - 3 * 128 * 32;
    if (j >= 0 && j < 128 * 128) {
        int n = j >> 7, k = j & 127;
        g_whT[12 * 16384 + j] = __float2half_rn((n < 64) ? aw1[k * 64 + n] : 0.0f);
    }
    if (j >= 0 && j < 128) {
        g_b1pad[j]  = (j < 64) ? ab1[j] : 0.0f;
        g_aw2pad[j] = (j < 64) ? aw2[j] : 0.0f;
    }
}

// ---------------- gather hf0 = embedF[r] ----------------
__global__ void k_hf0(const int* __restrict__ r) {
    int idx = blockIdx.x * 256 + threadIdx.x;
    if (idx >= N_ATOMS * 16) return;
    int atom = idx >> 4, q = idx & 15;
    ((uint4*)g_hf)[idx] = ((const uint4*)g_embedF)[(size_t)r[atom] * 16 + q];
}

// ================= GEMM building blocks =================
__device__ __forceinline__ void stage_A_f(const float* __restrict__ A, __half* As,
                                          int row0, int c, int M, int tid) {
    int ar = tid >> 1;
    int k0 = (tid & 1) * 32;
    const float* ap = A + (size_t)(row0 + ar) * 128 + c * 64 + k0;
    bool valid = (row0 + ar) < M;
    #pragma unroll
    for (int p = 0; p < 8; p++) {
        float4 v = make_float4(0.f, 0.f, 0.f, 0.f);
        if (valid) v = *(const float4*)(ap + p * 4);
        *(__half2*)&As[ar * 72 + k0 + p * 4]     = __floats2half2_rn(v.x, v.y);
        *(__half2*)&As[ar * 72 + k0 + p * 4 + 2] = __floats2half2_rn(v.z, v.w);
    }
}

__device__ __forceinline__ void stage_A_h(const __half* __restrict__ Ah, __half* As,
                                          int row0, int c, int M, int tid) {
    #pragma unroll
    for (int p = 0; p < 4; p++) {
        int idx = tid + p * 256;
        int m = idx >> 3, k8 = (idx & 7) * 8;
        uint4 v = make_uint4(0, 0, 0, 0);
        if (row0 + m < M) v = *(const uint4*)(Ah + (size_t)(row0 + m) * 128 + c * 64 + k8);
        *(uint4*)&As[m * 72 + k8] = v;
    }
}

__device__ __forceinline__ void stage_W_h(const __half* __restrict__ Wh, __half* Ws,
                                          int c, int tid) {
    #pragma unroll
    for (int p = 0; p < 4; p++) {
        int idx = tid + p * 256;
        int n = idx >> 3, k8 = (idx & 7) * 8;
        *(uint4*)&Ws[n * 72 + k8] = *(const uint4*)(Wh + (size_t)n * 128 + c * 64 + k8);
    }
}

__device__ __forceinline__ void mma_chunk(const __half* As, const __half* Ws,
                                          float acc[4][4][4], int wr, int wc, int g, int tig) {
    #pragma unroll
    for (int ks = 0; ks < 64; ks += 16) {
        unsigned af[4][4], bf[4][2];
        #pragma unroll
        for (int i = 0; i < 4; i++) {
            int r = wr * 64 + i * 16 + g;
            af[i][0] = *(const unsigned*)&As[r * 72 + ks + tig * 2];
            af[i][1] = *(const unsigned*)&As[(r + 8) * 72 + ks + tig * 2];
            af[i][2] = *(const unsigned*)&As[r * 72 + ks + tig * 2 + 8];
            af[i][3] = *(const unsigned*)&As[(r + 8) * 72 + ks + tig * 2 + 8];
        }
        #pragma unroll
        for (int jf = 0; jf < 4; jf++) {
            int n = wc * 32 + jf * 8 + g;
            bf[jf][0] = *(const unsigned*)&Ws[n * 72 + ks + tig * 2];
            bf[jf][1] = *(const unsigned*)&Ws[n * 72 + ks + tig * 2 + 8];
        }
        #pragma unroll
        for (int i = 0; i < 4; i++)
            #pragma unroll
            for (int jf = 0; jf < 4; jf++)
                mma_f16(acc[i][jf], af[i], bf[jf]);
    }
}

#define ZERO_ACC(acc) { _Pragma("unroll") for (int i = 0; i < 4; i++) _Pragma("unroll") \
    for (int jf = 0; jf < 4; jf++) _Pragma("unroll") for (int q = 0; q < 4; q++) acc[i][jf][q] = 0.0f; }

// ---------------- fused table build (dynamic smem; Ts stride 136) ----------------
#define TBL_SMEM (128 * 40 * 2 + 128 * 136 * 2 + 128 * 72 * 2 + 512 + 512)
__global__ __launch_bounds__(256) void k_tbl(const float* __restrict__ fb1,
                                             const float* __restrict__ fb2) {
    extern __shared__ char dsm[];
    __half* Gs = (__half*)dsm;                          // [m][k=32] stride 40
    __half* Ts = (__half*)(dsm + 10240);                // [m][k=128] stride 136
    __half* Ws = (__half*)(dsm + 10240 + 34816);        // [n][k] stride 72 (or 40 in GEMM1)
    float* bs1 = (float*)(dsm + 10240 + 34816 + 18432);
    float* bs2 = (float*)(dsm + 10240 + 34816 + 18432 + 512);
    int tid = threadIdx.x;
    int lane = tid & 31, wid = tid >> 5;
    int wr = wid >> 2, wc = wid & 3;
    int g = lane >> 2, tig = lane & 3;
    int L = blockIdx.x / (TBL / 128);
    int e0 = (blockIdx.x % (TBL / 128)) * 128;
    float width = 5.0f / 31.0f;
    float coeff = -0.5f / (width * width);
    for (int i = tid; i < 128 * 32; i += 256) {
        int m = i >> 5, k = i & 31;
        float d = (float)(e0 + m) * (DMAXF / (float)(TBL - 1));
        float x = d - (float)k * width;
        Gs[m * 40 + k] = __float2half_rn(expf(coeff * x * x));
    }
    if (tid < 128) { bs1[tid] = fb1[L * 128 + tid]; bs2[tid] = fb2[L * 128 + tid]; }
    for (int i = tid; i < 128 * 4; i += 256) {
        int n = i >> 2, k8 = (i & 3) * 8;
        *(uint4*)&Ws[n * 40 + k8] = *(const uint4*)&g_w1T[(size_t)(L * 128 + n) * 32 + k8];
    }
    __syncthreads();
    float acc[4][4][4];
    ZERO_ACC(acc);
    #pragma unroll
    for (int ks = 0; ks < 32; ks += 16) {
        unsigned af[4][4], bf[4][2];
        #pragma unroll
        for (int i = 0; i < 4; i++) {
            int r = wr * 64 + i * 16 + g;
            af[i][0] = *(const unsigned*)&Gs[r * 40 + ks + tig * 2];
            af[i][1] = *(const unsigned*)&Gs[(r + 8) * 40 + ks + tig * 2];
            af[i][2] = *(const unsigned*)&Gs[r * 40 + ks + tig * 2 + 8];
            af[i][3] = *(const unsigned*)&Gs[(r + 8) * 40 + ks + tig * 2 + 8];
        }
        #pragma unroll
        for (int jf = 0; jf < 4; jf++) {
            int n = wc * 32 + jf * 8 + g;
            bf[jf][0] = *(const unsigned*)&Ws[n * 40 + ks + tig * 2];
            bf[jf][1] = *(const unsigned*)&Ws[n * 40 + ks + tig * 2 + 8];
        }
        #pragma unroll
        for (int i = 0; i < 4; i++)
            #pragma unroll
            for (int jf = 0; jf < 4; jf++)
                mma_f16(acc[i][jf], af[i], bf[jf]);
    }
    #pragma unroll
    for (int i = 0; i < 4; i++) {
        #pragma unroll
        for (int jf = 0; jf < 4; jf++) {
            int n = wc * 32 + jf * 8 + 2 * tig;
            #pragma unroll
            for (int hh = 0; hh < 2; hh++) {
                int rloc = wr * 64 + i * 16 + g + hh * 8;
                float v0 = sspf(acc[i][jf][hh * 2 + 0] + bs1[n]);
                float v1 = sspf(acc[i][jf][hh * 2 + 1] + bs1[n + 1]);
                *(__half2*)&Ts[rloc * 136 + n] = __floats2half2_rn(v0, v1);
            }
        }
    }
    ZERO_ACC(acc);
    const __half* w2T = g_whT + (size_t)(9 + L) * 16384;
    for (int c = 0; c < 2; c++) {
        __syncthreads();
        stage_W_h(w2T, Ws, c, tid);
        __syncthreads();
        #pragma unroll
        for (int ks = 0; ks < 64; ks += 16) {
            unsigned af[4][4], bf[4][2];
            #pragma unroll
            for (int i = 0; i < 4; i++) {
                int r = wr * 64 + i * 16 + g;
                af[i][0] = *(const unsigned*)&Ts[r * 136 + c * 64 + ks + tig * 2];
                af[i][1] = *(const unsigned*)&Ts[(r + 8) * 136 + c * 64 + ks + tig * 2];
                af[i][2] = *(const unsigned*)&Ts[r * 136 + c * 64 + ks + tig * 2 + 8];
                af[i][3] = *(const unsigned*)&Ts[(r + 8) * 136 + c * 64 + ks + tig * 2 + 8];
            }
            #pragma unroll
            for (int jf = 0; jf < 4; jf++) {
                int n = wc * 32 + jf * 8 + g;
                bf[jf][0] = *(const unsigned*)&Ws[n * 72 + ks + tig * 2];
                bf[jf][1] = *(const unsigned*)&Ws[n * 72 + ks + tig * 2 + 8];
            }
            #pragma unroll
            for (int i = 0; i < 4; i++)
                #pragma unroll
                for (int jf = 0; jf < 4; jf++)
                    mma_f16(acc[i][jf], af[i], bf[jf]);
        }
    }
    __half* trow = g_table + ((size_t)L * TBL + e0) * 128;
    #pragma unroll
    for (int i = 0; i < 4; i++) {
        #pragma unroll
        for (int jf = 0; jf < 4; jf++) {
            int n = wc * 32 + jf * 8 + 2 * tig;
            #pragma unroll
            for (int hh = 0; hh < 2; hh++) {
                int rloc = wr * 64 + i * 16 + g + hh * 8;
                float v0 = acc[i][jf][hh * 2 + 0] + bs2[n];
                float v1 = acc[i][jf][hh * 2 + 1] + bs2[n + 1];
                *(__half2*)&trow[(size_t)rloc * 128 + n] = __floats2half2_rn(v0, v1);
            }
        }
    }
}

// ---------------- aggregation: 4 edges/iter, 8-lane feature groups (2 uint4/lane) ----------------
__global__ __launch_bounds__(256) void k_agg(const __half* __restrict__ tbl) {
    int atom = blockIdx.x * 8 + threadIdx.y;
    int lane = threadIdx.x;
    int hid = lane >> 3;               // 0..3: edge group
    int fl = lane & 7;                 // covers uint4 slots fl and fl+8
    int s = g_start[atom], c = g_counts[atom];
    float acc[16];
    #pragma unroll
    for (int q = 0; q < 16; q++) acc[q] = 0.0f;
    const uint4* t4 = (const uint4*)tbl;
    const uint4* h4 = (const uint4*)g_hf;
    #pragma unroll 2
    for (int e = hid; e < c; e += 4) {
        unsigned m = __ldg(&g_metap[s + e]);
        int src = m & 0x1FFFF;
        int i0 = m >> 17;
        uint4 wv0 = __ldg(&t4[(size_t)i0 * 16 + fl]);
        uint4 wv1 = __ldg(&t4[(size_t)i0 * 16 + fl + 8]);
        uint4 hv0 = __ldg(&h4[(size_t)src * 16 + fl]);
        uint4 hv1 = __ldg(&h4[(size_t)src * 16 + fl + 8]);
        const __half2* wp0 = (const __half2*)&wv0;
        const __half2* hp0 = (const __half2*)&hv0;
        const __half2* wp1 = (const __half2*)&wv1;
        const __half2* hp1 = (const __half2*)&hv1;
        #pragma unroll
        for (int q = 0; q < 4; q++) {
            float2 wf = __half22float2(wp0[q]);
            float2 hf = __half22float2(hp0[q]);
            acc[2 * q]     = fmaf(hf.x, wf.x, acc[2 * q]);
            acc[2 * q + 1] = fmaf(hf.y, wf.y, acc[2 * q + 1]);
            float2 wg = __half22float2(wp1[q]);
            float2 hg = __half22float2(hp1[q]);
            acc[8 + 2 * q]     = fmaf(hg.x, wg.x, acc[8 + 2 * q]);
            acc[8 + 2 * q + 1] = fmaf(hg.y, wg.y, acc[8 + 2 * q + 1]);
        }
    }
    #pragma unroll
    for (int q = 0; q < 16; q++) {
        acc[q] += __shfl_xor_sync(0xffffffffu, acc[q], 8);
        acc[q] += __shfl_xor_sync(0xffffffffu, acc[q], 16);
    }
    if (hid == 0) {
        uint4 st0, st1;
        __half2* sp0 = (__half2*)&st0;
        __half2* sp1 = (__half2*)&st1;
        #pragma unroll
        for (int q = 0; q < 4; q++) {
            sp0[q] = __floats2half2_rn(acc[2 * q], acc[2 * q + 1]);
            sp1[q] = __floats2half2_rn(acc[8 + 2 * q], acc[8 + 2 * q + 1]);
        }
        ((uint4*)g_aggh)[(size_t)atom * 16 + fl] = st0;
        ((uint4*)g_aggh)[(size_t)atom * 16 + fl + 8] = st1;
    }
}

// ---------------- generic GEMM: fp32-A, half-W -> half out (embedF) ----------------
__global__ __launch_bounds__(256) void k_gemm(const float* __restrict__ A,
                                              const __half* __restrict__ Wh,
                                              const float* __restrict__ bias,
                                              __half* __restrict__ Ch, int M) {
    __shared__ __half As[128 * 72];
    __shared__ __half Ws[128 * 72];
    __shared__ float bs[128];
    int tid = threadIdx.x;
    int lane = tid & 31, wid = tid >> 5;
    int wr = wid >> 2, wc = wid & 3;
    int g = lane >> 2, tig = lane & 3;
    int row0 = blockIdx.x * 128;
    float acc[4][4][4];
    ZERO_ACC(acc);
    if (tid < 128) bs[tid] = bias[tid];

    for (int c = 0; c < 2; c++) {
        stage_A_f(A, As, row0, c, M, tid);
        stage_W_h(Wh, Ws, c, tid);
        __syncthreads();
        mma_chunk(As, Ws, acc, wr, wc, g, tig);
        __syncthreads();
    }
    #pragma unroll
    for (int i = 0; i < 4; i++) {
        int rbase = row0 + wr * 64 + i * 16 + g;
        #pragma unroll
        for (int jf = 0; jf < 4; jf++) {
            int n = wc * 32 + jf * 8 + 2 * tig;
            #pragma unroll
            for (int hh = 0; hh < 2; hh++) {
                int r = rbase + hh * 8;
                if (r >= M) continue;
                float v0 = acc[i][jf][hh * 2 + 0] + bs[n];
                float v1 = acc[i][jf][hh * 2 + 1] + bs[n + 1];
                *(__half2*)(Ch + (size_t)r * 128 + n) = __floats2half2_rn(v0, v1);
            }
        }
    }
}

// ---------------- fused layer: t1=ssp(aggh@W1+b1); h+=t1@W2+b2; then GEMM3 ----------------
// MODE 1: GEMM3 = h@Wn+bn -> HF (next layer's features)
// MODE 2: GEMM3 = ssp(h@w1pad+b1pad) . aw2pad + ab2 -> block-sum into out (fused readout)
template <int MODE>
__global__ __launch_bounds__(256) void k_fused(const __half* __restrict__ Ah,
                                               const __half* __restrict__ W1h,
                                               const float* __restrict__ b1,
                                               const __half* __restrict__ W2h,
                                               const float* __restrict__ b2,
                                               float* __restrict__ H,
                                               const __half* __restrict__ Wnh,
                                               const float* __restrict__ bn,
                                               __half* __restrict__ HF,
                                               const float* __restrict__ ab2,
                                               float* __restrict__ out,
                                               const int* __restrict__ nper, int M) {
    extern __shared__ char dsm[];
    __half* As0 = (__half*)dsm;
    __half* As1 = (__half*)(dsm + 18432);
    __half* Ws  = (__half*)(dsm + 36864);
    float*  fs  = (float*)(dsm + 55296);   // b1 | b2 | bn/b1pad | aw2 | srow
    __half* Asc[2] = {As0, As1};
    int tid = threadIdx.x;
    int lane = tid & 31, wid = tid >> 5;
    int wr = wid >> 2, wc = wid & 3;
    int g = lane >> 2, tig = lane & 3;
    int row0 = blockIdx.x * 128;
    if (tid < 128) {
        fs[tid] = b1[tid];
        fs[128 + tid] = b2[tid];
        fs[256 + tid] = bn[tid];
        if (MODE == 2) { fs[384 + tid] = g_aw2pad[tid]; fs[512 + tid] = 0.0f; }
    }

    // ---- GEMM1: t1 = ssp(agg @ W1 + b1) ----
    float acc[4][4][4];
    ZERO_ACC(acc);
    for (int c = 0; c < 2; c++) {
        stage_A_h(Ah, Asc[c], row0, c, M, tid);
        stage_W_h(W1h, Ws, c, tid);
        __syncthreads();
        mma_chunk(Asc[c], Ws, acc, wr, wc, g, tig);
        __syncthreads();
    }
    #pragma unroll
    for (int i = 0; i < 4; i++) {
        #pragma unroll
        for (int jf = 0; jf < 4; jf++) {
            int n = wc * 32 + jf * 8 + 2 * tig;
            #pragma unroll
            for (int hh = 0; hh < 2; hh++) {
                int rloc = wr * 64 + i * 16 + g + hh * 8;
                float v0 = sspf(acc[i][jf][hh * 2 + 0] + fs[n]);
                float v1 = sspf(acc[i][jf][hh * 2 + 1] + fs[n + 1]);
                *(__half2*)&Asc[n >> 6][rloc * 72 + (n & 63)] = __floats2half2_rn(v0, v1);
            }
        }
    }
    // ---- GEMM2: h_new = h + t1 @ W2 + b2 ----
    ZERO_ACC(acc);
    for (int c = 0; c < 2; c++) {
        stage_W_h(W2h, Ws, c, tid);
        __syncthreads();
        mma_chunk(Asc[c], Ws, acc, wr, wc, g, tig);
        __syncthreads();
    }
    #pragma unroll
    for (int i = 0; i < 4; i++) {
        #pragma unroll
        for (int jf = 0; jf < 4; jf++) {
            int n = wc * 32 + jf * 8 + 2 * tig;
            #pragma unroll
            for (int hh = 0; hh < 2; hh++) {
                int rloc = wr * 64 + i * 16 + g + hh * 8;
                int r = row0 + rloc;
                float v0 = acc[i][jf][hh * 2 + 0] + fs[128 + n];
                float v1 = acc[i][jf][hh * 2 + 1] + fs[128 + n + 1];
                if (r < M) {
                    float2 hold = *(const float2*)(H + (size_t)r * 128 + n);
                    v0 += hold.x; v1 += hold.y;
                    if (MODE == 1) {
                        float2 st; st.x = v0; st.y = v1;
                        *(float2*)(H + (size_t)r * 128 + n) = st;
                    }
                }
                *(__half2*)&Asc[n >> 6][rloc * 72 + (n & 63)] = __floats2half2_rn(v0, v1);
            }
        }
    }
    // ---- GEMM3 ----
    ZERO_ACC(acc);
    for (int c = 0; c < 2; c++) {
        stage_W_h(Wnh, Ws, c, tid);
        __syncthreads();
        mma_chunk(Asc[c], Ws, acc, wr, wc, g, tig);
        __syncthreads();
    }
    if (MODE == 1) {
        #pragma unroll
        for (int i = 0; i < 4; i++) {
            #pragma unroll
            for (int jf = 0; jf < 4; jf++) {
                int n = wc * 32 + jf * 8 + 2 * tig;
                #pragma unroll
                for (int hh = 0; hh < 2; hh++) {
                    int r = row0 + wr * 64 + i * 16 + g + hh * 8;
                    if (r >= M) continue;
                    float v0 = acc[i][jf][hh * 2 + 0] + fs[256 + n];
                    float v1 = acc[i][jf][hh * 2 + 1] + fs[256 + n + 1];
                    *(__half2*)(HF + (size_t)r * 128 + n) = __floats2half2_rn(v0, v1);
                }
            }
        }
    } else {
        int np = nper ? __ldg(nper) : 5000;
        float ab2v = __ldg(ab2);
        #pragma unroll
        for (int i = 0; i < 4; i++) {
            #pragma unroll
            for (int hh = 0; hh < 2; hh++) {
                int rloc = wr * 64 + i * 16 + g + hh * 8;
                float s = 0.0f;
                #pragma unroll
                for (int jf = 0; jf < 4; jf++) {
                    int n = wc * 32 + jf * 8 + 2 * tig;
                    float v0 = sspf(acc[i][jf][hh * 2 + 0] + fs[256 + n]);
                    float v1 = sspf(acc[i][jf][hh * 2 + 1] + fs[256 + n + 1]);
                    s += v0 * fs[384 + n] + v1 * fs[384 + n + 1];
                }
                atomicAdd(&fs[512 + rloc], s);
            }
        }
        __syncthreads();
        if (tid < 128) {
            int r = row0 + tid;
            if (r < M) atomicAdd(&out[r / np], fs[512 + tid] + ab2v);
        }
    }
}

// ---------------- host ----------------
extern "C" void kernel_launch(void* const* d_in, const int* in_sizes, int n_in,
                              void* d_out, int out_size) {
    const int*   r   = (const int*)d_in[0];
    const float* xyz = (const float*)d_in[1];
    const int*   a   = (const int*)d_in[2];
    int base = 3;
    const int* nper = nullptr;
    if (n_in >= 19) { nper = (const int*)d_in[3]; base = 4; }
    const float* embed = (const float*)d_in[base + 0];
    const float* fw1   = (const float*)d_in[base + 1];
    const float* fb1   = (const float*)d_in[base + 2];
    const float* fw2   = (const float*)d_in[base + 3];
    const float* fb2   = (const float*)d_in[base + 4];
    const float* afw   = (const float*)d_in[base + 5];
    const float* afb   = (const float*)d_in[base + 6];
    const float* ow1   = (const float*)d_in[base + 7];
    const float* ob1   = (const float*)d_in[base + 8];
    const float* ow2   = (const float*)d_in[base + 9];
    const float* ob2   = (const float*)d_in[base + 10];
    const float* aw1   = (const float*)d_in[base + 11];
    const float* ab1   = (const float*)d_in[base + 12];
    const float* aw2   = (const float*)d_in[base + 13];
    const float* ab2   = (const float*)d_in[base + 14];
    float* out = (float*)d_out;

    float *ph, *pb1pad;
    __half *phf, *paggh, *ptbl, *pwhT, *pembedF;
    cudaGetSymbolAddress((void**)&ph,      g_h);
    cudaGetSymbolAddress((void**)&phf,     g_hf);
    cudaGetSymbolAddress((void**)&paggh,   g_aggh);
    cudaGetSymbolAddress((void**)&ptbl,    g_table);
    cudaGetSymbolAddress((void**)&pwhT,    g_whT);
    cudaGetSymbolAddress((void**)&pembedF, g_embedF);
    cudaGetSymbolAddress((void**)&pb1pad,  g_b1pad);

    const int FUSED_SMEM = 57856;
    cudaFuncSetAttribute(k_fused<1>, cudaFuncAttributeMaxDynamicSharedMemorySize, FUSED_SMEM);
    cudaFuncSetAttribute(k_fused<2>, cudaFuncAttributeMaxDynamicSharedMemorySize, FUSED_SMEM);
    cudaFuncSetAttribute(k_tbl, cudaFuncAttributeMaxDynamicSharedMemorySize, TBL_SMEM);

    k_init<<<(N_ATOMS * 32 + 255) / 256, 256>>>(r, embed, out, out_size);
    k_edges<<<(N_EDGES + 255) / 256, 256>>>(a, xyz);
    k_scan<<<1, 1024>>>();
    k_scatter<<<(N_EDGES + 255) / 256, 256>>>(a);
    k_prep<<<dim3(4, 4, 12), dim3(32, 8)>>>(ow1, ow2, afw, fw2);
    k_prepsmall<<<(3 * 128 * 32 + 128 * 128 + 255) / 256, 256>>>(fw1, aw1, ab1, aw2);
    k_tbl<<<3 * (TBL / 128), 256, TBL_SMEM>>>(fb1, fb2);

    // embedF = embed @ afw0 + afb0 (100 rows, one block), then hf0 = embedF[r]
    k_gemm<<<1, 256>>>(embed, pwhT + (size_t)6 * 16384, afb, pembedF, 100);
    k_hf0<<<(N_ATOMS * 16 + 255) / 256, 256>>>(r);

    int gemm_grid = (N_ATOMS + 127) / 128;
    for (int L = 0; L < 3; L++) {
        k_agg<<<N_ATOMS / 8, dim3(32, 8)>>>(ptbl + (size_t)L * TBL * 128);
        if (L < 2)
            k_fused<1><<<gemm_grid, 256, FUSED_SMEM>>>(
                paggh, pwhT + (size_t)L * 16384, ob1 + L * 128,
                pwhT + (size_t)(3 + L) * 16384, ob2 + L * 128, ph,
                pwhT + (size_t)(6 + L + 1) * 16384, afb + (L + 1) * 128, phf,
                nullptr, nullptr, nullptr, N_ATOMS);
        else
            k_fused<2><<<gemm_grid, 256, FUSED_SMEM>>>(
                paggh, pwhT + (size_t)L * 16384, ob1 + L * 128,
                pwhT + (size_t)(3 + L) * 16384, ob2 + L * 128, ph,
                pwhT + (size_t)12 * 16384, pb1pad, nullptr,
                ab2, out, nper, N_ATOMS);
    }
}

// round 14
// speedup vs baseline: 1.0383x; 1.0383x over previous
#include <cuda_runtime.h>
#include <cuda_fp16.h>
#include <math.h>

#define N_ATOMS 50000
#define N_EDGES 800000
#define TBL 8192
#define DMAXF 14.0f
#define LN2F 0.6931471805599453f

// ---------------- device scratch ----------------
__device__ float    g_h   [N_ATOMS * 128];
__device__ __half   g_hf  [N_ATOMS * 128];
__device__ __half   g_aggh[N_ATOMS * 128];
__device__ float    g_d   [N_EDGES];
__device__ unsigned g_metap[N_EDGES];        // src (17b) | table-index << 17
__device__ int      g_counts[N_ATOMS];
__device__ int      g_start [N_ATOMS];
__device__ int      g_cursor[N_ATOMS];
__device__ __half   g_table[3 * TBL * 128];
__device__ __half   g_whT  [13 * 128 * 128]; // [n][k]: 0-2 ow1, 3-5 ow2, 6-8 afw, 9-11 fw2, 12 w1pad
__device__ __half   g_w1T  [3 * 128 * 32];   // fw1 transposed [n=128][k=32]
__device__ __half   g_embedF[128 * 128];     // embed @ afw0 + afb0 (100 rows used)
__device__ float    g_b1pad[128];
__device__ float    g_aw2pad[128];

__device__ __forceinline__ float sspf(float x) {
    return fmaxf(x, 0.0f) + log1pf(expf(-fabsf(x))) - LN2F;
}

__device__ __forceinline__ void mma_f16(float* d, const unsigned* a, const unsigned* b) {
    asm volatile(
        "mma.sync.aligned.m16n8k16.row.col.f32.f16.f16.f32 "
        "{%0,%1,%2,%3}, {%4,%5,%6,%7}, {%8,%9}, {%0,%1,%2,%3};\n"
        : "+f"(d[0]), "+f"(d[1]), "+f"(d[2]), "+f"(d[3])
        : "r"(a[0]), "r"(a[1]), "r"(a[2]), "r"(a[3]), "r"(b[0]), "r"(b[1]));
}

// ---------------- init ----------------
__global__ void k_init(const int* __restrict__ r, const float* __restrict__ embed,
                       float* __restrict__ out, int out_size) {
    int idx = blockIdx.x * blockDim.x + threadIdx.x;
    if (idx < N_ATOMS * 32) {
        int atom = idx >> 5, j = idx & 31;
        ((float4*)g_h)[atom * 32 + j] = ((const float4*)embed)[(size_t)r[atom] * 32 + j];
    }
    if (idx < N_ATOMS) g_counts[idx] = 0;
    if (idx < out_size) out[idx] = 0.0f;
}

// ---------------- edges ----------------
__global__ void k_edges(const int* __restrict__ a, const float* __restrict__ xyz) {
    int e = blockIdx.x * blockDim.x + threadIdx.x;
    if (e >= N_EDGES) return;
    int d0 = a[2 * e], s0 = a[2 * e + 1];
    float dx = xyz[3 * d0 + 0] - xyz[3 * s0 + 0];
    float dy = xyz[3 * d0 + 1] - xyz[3 * s0 + 1];
    float dz = xyz[3 * d0 + 2] - xyz[3 * s0 + 2];
    g_d[e] = sqrtf(dx * dx + dy * dy + dz * dz + 1e-12f);
    atomicAdd(&g_counts[d0], 1);
}

// ---------------- exclusive scan ----------------
__global__ __launch_bounds__(1024) void k_scan() {
    __shared__ int wsum[32];
    __shared__ int carry;
    __shared__ int tot;
    int t = threadIdx.x, lane = t & 31, w = t >> 5;
    if (t == 0) carry = 0;
    __syncthreads();
    for (int base = 0; base < N_ATOMS; base += 1024) {
        int i = base + t;
        int v = (i < N_ATOMS) ? g_counts[i] : 0;
        int incl = v;
        #pragma unroll
        for (int off = 1; off < 32; off <<= 1) {
            int x = __shfl_up_sync(0xffffffffu, incl, off);
            if (lane >= off) incl += x;
        }
        if (lane == 31) wsum[w] = incl;
        __syncthreads();
        if (w == 0) {
            int s = wsum[lane];
            int si = s;
            #pragma unroll
            for (int off = 1; off < 32; off <<= 1) {
                int x = __shfl_up_sync(0xffffffffu, si, off);
                if (lane >= off) si += x;
            }
            wsum[lane] = si - s;
            if (lane == 31) tot = si;
        }
        __syncthreads();
        int excl = carry + wsum[w] + incl - v;
        if (i < N_ATOMS) { g_start[i] = excl; g_cursor[i] = excl; }
        __syncthreads();
        if (t == 0) carry += tot;
        __syncthreads();
    }
}

// ---------------- scatter: pack (src | i0<<17) ----------------
__global__ void k_scatter(const int* __restrict__ a) {
    int e = blockIdx.x * blockDim.x + threadIdx.x;
    if (e >= N_EDGES) return;
    int d0 = a[2 * e];
    int pos = atomicAdd(&g_cursor[d0], 1);
    float d = g_d[e];
    float u = d * ((float)(TBL - 1) / DMAXF);
    int i0 = (int)(u + 0.5f);
    i0 = min(i0, TBL - 1);
    g_metap[pos] = (unsigned)a[2 * e + 1] | ((unsigned)i0 << 17);
}

// ---------------- weight transpose+convert: fp32 [k][n] -> half [n][k] ----------------
__global__ void k_prep(const float* __restrict__ ow1, const float* __restrict__ ow2,
                       const float* __restrict__ afw, const float* __restrict__ fw2) {
    __shared__ float t[32][33];
    int mat = blockIdx.z;
    const float* src = (mat < 3) ? ow1 + (size_t)mat * 16384
                     : (mat < 6) ? ow2 + (size_t)(mat - 3) * 16384
                     : (mat < 9) ? afw + (size_t)(mat - 6) * 16384
                                 : fw2 + (size_t)(mat - 9) * 16384;
    __half* dst = g_whT + (size_t)mat * 16384;
    int k0 = blockIdx.y * 32, n0 = blockIdx.x * 32;
    int tx = threadIdx.x, ty = threadIdx.y;   // (32, 8)
    #pragma unroll
    for (int q = 0; q < 4; q++)
        t[ty + q * 8][tx] = src[(size_t)(k0 + ty + q * 8) * 128 + n0 + tx];
    __syncthreads();
    #pragma unroll
    for (int q = 0; q < 4; q++)
        dst[(size_t)(n0 + ty + q * 8) * 128 + k0 + tx] = __float2half_rn(t[tx][ty + q * 8]);
}

// ---------------- small prep: fw1 transpose + readout pads (merged) ----------------
__global__ void k_prepsmall(const float* __restrict__ fw1, const float* __restrict__ aw1,
                            const float* __restrict__ ab1, const float* __restrict__ aw2) {
    int i = blockIdx.x * 256 + threadIdx.x;
    if (i < 3 * 128 * 32) {
        int L = i >> 12, rest = i & 4095, n = rest >> 5, k = rest & 31;
        g_w1T[i] = __float2half_rn(fw1[L * 4096 + k * 128 + n]);
    }
    int j = i - 3 * 128 * 32;
    if (j >= 0 && j < 128 * 128) {
        int n = j >> 7, k = j & 127;
        g_whT[12 * 16384 + j] = __float2half_rn((n < 64) ? aw1[k * 64 + n] : 0.0f);
    }
    if (j >= 0 && j < 128) {
        g_b1pad[j]  = (j < 64) ? ab1[j] : 0.0f;
        g_aw2pad[j] = (j < 64) ? aw2[j] : 0.0f;
    }
}

// ---------------- gather hf0 = embedF[r] ----------------
__global__ void k_hf0(const int* __restrict__ r) {
    int idx = blockIdx.x * 256 + threadIdx.x;
    if (idx >= N_ATOMS * 16) return;
    int atom = idx >> 4, q = idx & 15;
    ((uint4*)g_hf)[idx] = ((const uint4*)g_embedF)[(size_t)r[atom] * 16 + q];
}

// ================= GEMM building blocks =================
__device__ __forceinline__ void stage_A_f(const float* __restrict__ A, __half* As,
                                          int row0, int c, int M, int tid) {
    int ar = tid >> 1;
    int k0 = (tid & 1) * 32;
    const float* ap = A + (size_t)(row0 + ar) * 128 + c * 64 + k0;
    bool valid = (row0 + ar) < M;
    #pragma unroll
    for (int p = 0; p < 8; p++) {
        float4 v = make_float4(0.f, 0.f, 0.f, 0.f);
        if (valid) v = *(const float4*)(ap + p * 4);
        *(__half2*)&As[ar * 72 + k0 + p * 4]     = __floats2half2_rn(v.x, v.y);
        *(__half2*)&As[ar * 72 + k0 + p * 4 + 2] = __floats2half2_rn(v.z, v.w);
    }
}

__device__ __forceinline__ void stage_A_h(const __half* __restrict__ Ah, __half* As,
                                          int row0, int c, int M, int tid) {
    #pragma unroll
    for (int p = 0; p < 4; p++) {
        int idx = tid + p * 256;
        int m = idx >> 3, k8 = (idx & 7) * 8;
        uint4 v = make_uint4(0, 0, 0, 0);
        if (row0 + m < M) v = *(const uint4*)(Ah + (size_t)(row0 + m) * 128 + c * 64 + k8);
        *(uint4*)&As[m * 72 + k8] = v;
    }
}

__device__ __forceinline__ void stage_W_h(const __half* __restrict__ Wh, __half* Ws,
                                          int c, int tid) {
    #pragma unroll
    for (int p = 0; p < 4; p++) {
        int idx = tid + p * 256;
        int n = idx >> 3, k8 = (idx & 7) * 8;
        *(uint4*)&Ws[n * 72 + k8] = *(const uint4*)(Wh + (size_t)n * 128 + c * 64 + k8);
    }
}

__device__ __forceinline__ void mma_chunk(const __half* As, const __half* Ws,
                                          float acc[4][4][4], int wr, int wc, int g, int tig) {
    #pragma unroll
    for (int ks = 0; ks < 64; ks += 16) {
        unsigned af[4][4], bf[4][2];
        #pragma unroll
        for (int i = 0; i < 4; i++) {
            int r = wr * 64 + i * 16 + g;
            af[i][0] = *(const unsigned*)&As[r * 72 + ks + tig * 2];
            af[i][1] = *(const unsigned*)&As[(r + 8) * 72 + ks + tig * 2];
            af[i][2] = *(const unsigned*)&As[r * 72 + ks + tig * 2 + 8];
            af[i][3] = *(const unsigned*)&As[(r + 8) * 72 + ks + tig * 2 + 8];
        }
        #pragma unroll
        for (int jf = 0; jf < 4; jf++) {
            int n = wc * 32 + jf * 8 + g;
            bf[jf][0] = *(const unsigned*)&Ws[n * 72 + ks + tig * 2];
            bf[jf][1] = *(const unsigned*)&Ws[n * 72 + ks + tig * 2 + 8];
        }
        #pragma unroll
        for (int i = 0; i < 4; i++)
            #pragma unroll
            for (int jf = 0; jf < 4; jf++)
                mma_f16(acc[i][jf], af[i], bf[jf]);
    }
}

#define ZERO_ACC(acc) { _Pragma("unroll") for (int i = 0; i < 4; i++) _Pragma("unroll") \
    for (int jf = 0; jf < 4; jf++) _Pragma("unroll") for (int q = 0; q < 4; q++) acc[i][jf][q] = 0.0f; }

// ---------------- fused table build (dynamic smem; Ts stride 136) ----------------
#define TBL_SMEM (128 * 40 * 2 + 128 * 136 * 2 + 128 * 72 * 2 + 512 + 512)
__global__ __launch_bounds__(256) void k_tbl(const float* __restrict__ fb1,
                                             const float* __restrict__ fb2) {
    extern __shared__ char dsm[];
    __half* Gs = (__half*)dsm;                          // [m][k=32] stride 40
    __half* Ts = (__half*)(dsm + 10240);                // [m][k=128] stride 136
    __half* Ws = (__half*)(dsm + 10240 + 34816);        // [n][k] stride 72 (or 40 in GEMM1)
    float* bs1 = (float*)(dsm + 10240 + 34816 + 18432);
    float* bs2 = (float*)(dsm + 10240 + 34816 + 18432 + 512);
    int tid = threadIdx.x;
    int lane = tid & 31, wid = tid >> 5;
    int wr = wid >> 2, wc = wid & 3;
    int g = lane >> 2, tig = lane & 3;
    int L = blockIdx.x / (TBL / 128);
    int e0 = (blockIdx.x % (TBL / 128)) * 128;
    float width = 5.0f / 31.0f;
    float coeff = -0.5f / (width * width);
    for (int i = tid; i < 128 * 32; i += 256) {
        int m = i >> 5, k = i & 31;
        float d = (float)(e0 + m) * (DMAXF / (float)(TBL - 1));
        float x = d - (float)k * width;
        Gs[m * 40 + k] = __float2half_rn(expf(coeff * x * x));
    }
    if (tid < 128) { bs1[tid] = fb1[L * 128 + tid]; bs2[tid] = fb2[L * 128 + tid]; }
    for (int i = tid; i < 128 * 4; i += 256) {
        int n = i >> 2, k8 = (i & 3) * 8;
        *(uint4*)&Ws[n * 40 + k8] = *(const uint4*)&g_w1T[(size_t)(L * 128 + n) * 32 + k8];
    }
    __syncthreads();
    float acc[4][4][4];
    ZERO_ACC(acc);
    #pragma unroll
    for (int ks = 0; ks < 32; ks += 16) {
        unsigned af[4][4], bf[4][2];
        #pragma unroll
        for (int i = 0; i < 4; i++) {
            int r = wr * 64 + i * 16 + g;
            af[i][0] = *(const unsigned*)&Gs[r * 40 + ks + tig * 2];
            af[i][1] = *(const unsigned*)&Gs[(r + 8) * 40 + ks + tig * 2];
            af[i][2] = *(const unsigned*)&Gs[r * 40 + ks + tig * 2 + 8];
            af[i][3] = *(const unsigned*)&Gs[(r + 8) * 40 + ks + tig * 2 + 8];
        }
        #pragma unroll
        for (int jf = 0; jf < 4; jf++) {
            int n = wc * 32 + jf * 8 + g;
            bf[jf][0] = *(const unsigned*)&Ws[n * 40 + ks + tig * 2];
            bf[jf][1] = *(const unsigned*)&Ws[n * 40 + ks + tig * 2 + 8];
        }
        #pragma unroll
        for (int i = 0; i < 4; i++)
            #pragma unroll
            for (int jf = 0; jf < 4; jf++)
                mma_f16(acc[i][jf], af[i], bf[jf]);
    }
    #pragma unroll
    for (int i = 0; i < 4; i++) {
        #pragma unroll
        for (int jf = 0; jf < 4; jf++) {
            int n = wc * 32 + jf * 8 + 2 * tig;
            #pragma unroll
            for (int hh = 0; hh < 2; hh++) {
                int rloc = wr * 64 + i * 16 + g + hh * 8;
                float v0 = sspf(acc[i][jf][hh * 2 + 0] + bs1[n]);
                float v1 = sspf(acc[i][jf][hh * 2 + 1] + bs1[n + 1]);
                *(__half2*)&Ts[rloc * 136 + n] = __floats2half2_rn(v0, v1);
            }
        }
    }
    ZERO_ACC(acc);
    const __half* w2T = g_whT + (size_t)(9 + L) * 16384;
    for (int c = 0; c < 2; c++) {
        __syncthreads();
        stage_W_h(w2T, Ws, c, tid);
        __syncthreads();
        #pragma unroll
        for (int ks = 0; ks < 64; ks += 16) {
            unsigned af[4][4], bf[4][2];
            #pragma unroll
            for (int i = 0; i < 4; i++) {
                int r = wr * 64 + i * 16 + g;
                af[i][0] = *(const unsigned*)&Ts[r * 136 + c * 64 + ks + tig * 2];
                af[i][1] = *(const unsigned*)&Ts[(r + 8) * 136 + c * 64 + ks + tig * 2];
                af[i][2] = *(const unsigned*)&Ts[r * 136 + c * 64 + ks + tig * 2 + 8];
                af[i][3] = *(const unsigned*)&Ts[(r + 8) * 136 + c * 64 + ks + tig * 2 + 8];
            }
            #pragma unroll
            for (int jf = 0; jf < 4; jf++) {
                int n = wc * 32 + jf * 8 + g;
                bf[jf][0] = *(const unsigned*)&Ws[n * 72 + ks + tig * 2];
                bf[jf][1] = *(const unsigned*)&Ws[n * 72 + ks + tig * 2 + 8];
            }
            #pragma unroll
            for (int i = 0; i < 4; i++)
                #pragma unroll
                for (int jf = 0; jf < 4; jf++)
                    mma_f16(acc[i][jf], af[i], bf[jf]);
        }
    }
    __half* trow = g_table + ((size_t)L * TBL + e0) * 128;
    #pragma unroll
    for (int i = 0; i < 4; i++) {
        #pragma unroll
        for (int jf = 0; jf < 4; jf++) {
            int n = wc * 32 + jf * 8 + 2 * tig;
            #pragma unroll
            for (int hh = 0; hh < 2; hh++) {
                int rloc = wr * 64 + i * 16 + g + hh * 8;
                float v0 = acc[i][jf][hh * 2 + 0] + bs2[n];
                float v1 = acc[i][jf][hh * 2 + 1] + bs2[n + 1];
                *(__half2*)&trow[(size_t)rloc * 128 + n] = __floats2half2_rn(v0, v1);
            }
        }
    }
}

// ---------------- aggregation: 2 edges/iter, 16B lanes, warp per atom ----------------
__global__ __launch_bounds__(256) void k_agg(const __half* __restrict__ tbl) {
    int atom = blockIdx.x * 8 + threadIdx.y;
    int lane = threadIdx.x;
    int hid = lane >> 4;               // 0: even edges, 1: odd edges
    int fl = lane & 15;                // features 8*fl .. 8*fl+7
    int s = g_start[atom], c = g_counts[atom];
    float acc[8];
    #pragma unroll
    for (int q = 0; q < 8; q++) acc[q] = 0.0f;
    const uint4* t4 = (const uint4*)tbl;
    const uint4* h4 = (const uint4*)g_hf;
    #pragma unroll 2
    for (int e = hid; e < c; e += 2) {
        unsigned m = __ldg(&g_metap[s + e]);
        int src = m & 0x1FFFF;
        int i0 = m >> 17;
        uint4 wv = __ldg(&t4[(size_t)i0 * 16 + fl]);
        uint4 hv = __ldg(&h4[(size_t)src * 16 + fl]);
        const __half2* wp = (const __half2*)&wv;
        const __half2* hp = (const __half2*)&hv;
        #pragma unroll
        for (int q = 0; q < 4; q++) {
            float2 wf = __half22float2(wp[q]);
            float2 hf = __half22float2(hp[q]);
            acc[2 * q]     = fmaf(hf.x, wf.x, acc[2 * q]);
            acc[2 * q + 1] = fmaf(hf.y, wf.y, acc[2 * q + 1]);
        }
    }
    #pragma unroll
    for (int q = 0; q < 8; q++) acc[q] += __shfl_down_sync(0xffffffffu, acc[q], 16);
    if (hid == 0) {
        uint4 st;
        __half2* sp = (__half2*)&st;
        #pragma unroll
        for (int q = 0; q < 4; q++) sp[q] = __floats2half2_rn(acc[2 * q], acc[2 * q + 1]);
        ((uint4*)g_aggh)[(size_t)atom * 16 + fl] = st;
    }
}

// ---------------- generic GEMM: fp32-A, half-W -> half out (embedF) ----------------
__global__ __launch_bounds__(256) void k_gemm(const float* __restrict__ A,
                                              const __half* __restrict__ Wh,
                                              const float* __restrict__ bias,
                                              __half* __restrict__ Ch, int M) {
    __shared__ __half As[128 * 72];
    __shared__ __half Ws[128 * 72];
    __shared__ float bs[128];
    int tid = threadIdx.x;
    int lane = tid & 31, wid = tid >> 5;
    int wr = wid >> 2, wc = wid & 3;
    int g = lane >> 2, tig = lane & 3;
    int row0 = blockIdx.x * 128;
    float acc[4][4][4];
    ZERO_ACC(acc);
    if (tid < 128) bs[tid] = bias[tid];

    for (int c = 0; c < 2; c++) {
        stage_A_f(A, As, row0, c, M, tid);
        stage_W_h(Wh, Ws, c, tid);
        __syncthreads();
        mma_chunk(As, Ws, acc, wr, wc, g, tig);
        __syncthreads();
    }
    #pragma unroll
    for (int i = 0; i < 4; i++) {
        int rbase = row0 + wr * 64 + i * 16 + g;
        #pragma unroll
        for (int jf = 0; jf < 4; jf++) {
            int n = wc * 32 + jf * 8 + 2 * tig;
            #pragma unroll
            for (int hh = 0; hh < 2; hh++) {
                int r = rbase + hh * 8;
                if (r >= M) continue;
                float v0 = acc[i][jf][hh * 2 + 0] + bs[n];
                float v1 = acc[i][jf][hh * 2 + 1] + bs[n + 1];
                *(__half2*)(Ch + (size_t)r * 128 + n) = __floats2half2_rn(v0, v1);
            }
        }
    }
}

// ---------------- fused layer: t1=ssp(aggh@W1+b1); h+=t1@W2+b2; then GEMM3 ----------------
// MODE 1: GEMM3 = h@Wn+bn -> HF (next layer's features)
// MODE 2: GEMM3 = ssp(h@w1pad+b1pad) . aw2pad + ab2 -> block-sum into out (fused readout)
template <int MODE>
__global__ __launch_bounds__(256) void k_fused(const __half* __restrict__ Ah,
                                               const __half* __restrict__ W1h,
                                               const float* __restrict__ b1,
                                               const __half* __restrict__ W2h,
                                               const float* __restrict__ b2,
                                               float* __restrict__ H,
                                               const __half* __restrict__ Wnh,
                                               const float* __restrict__ bn,
                                               __half* __restrict__ HF,
                                               const float* __restrict__ ab2,
                                               float* __restrict__ out,
                                               const int* __restrict__ nper, int M) {
    extern __shared__ char dsm[];
    __half* As0 = (__half*)dsm;
    __half* As1 = (__half*)(dsm + 18432);
    __half* Ws  = (__half*)(dsm + 36864);
    float*  fs  = (float*)(dsm + 55296);   // b1 | b2 | bn/b1pad | aw2 | srow
    __half* Asc[2] = {As0, As1};
    int tid = threadIdx.x;
    int lane = tid & 31, wid = tid >> 5;
    int wr = wid >> 2, wc = wid & 3;
    int g = lane >> 2, tig = lane & 3;
    int row0 = blockIdx.x * 128;
    if (tid < 128) {
        fs[tid] = b1[tid];
        fs[128 + tid] = b2[tid];
        fs[256 + tid] = bn[tid];
        if (MODE == 2) { fs[384 + tid] = g_aw2pad[tid]; fs[512 + tid] = 0.0f; }
    }

    // ---- GEMM1: t1 = ssp(agg @ W1 + b1) ----
    float acc[4][4][4];
    ZERO_ACC(acc);
    for (int c = 0; c < 2; c++) {
        stage_A_h(Ah, Asc[c], row0, c, M, tid);
        stage_W_h(W1h, Ws, c, tid);
        __syncthreads();
        mma_chunk(Asc[c], Ws, acc, wr, wc, g, tig);
        __syncthreads();
    }
    #pragma unroll
    for (int i = 0; i < 4; i++) {
        #pragma unroll
        for (int jf = 0; jf < 4; jf++) {
            int n = wc * 32 + jf * 8 + 2 * tig;
            #pragma unroll
            for (int hh = 0; hh < 2; hh++) {
                int rloc = wr * 64 + i * 16 + g + hh * 8;
                float v0 = sspf(acc[i][jf][hh * 2 + 0] + fs[n]);
                float v1 = sspf(acc[i][jf][hh * 2 + 1] + fs[n + 1]);
                *(__half2*)&Asc[n >> 6][rloc * 72 + (n & 63)] = __floats2half2_rn(v0, v1);
            }
        }
    }
    // ---- GEMM2: h_new = h + t1 @ W2 + b2 ----
    ZERO_ACC(acc);
    for (int c = 0; c < 2; c++) {
        stage_W_h(W2h, Ws, c, tid);
        __syncthreads();
        mma_chunk(Asc[c], Ws, acc, wr, wc, g, tig);
        __syncthreads();
    }
    #pragma unroll
    for (int i = 0; i < 4; i++) {
        #pragma unroll
        for (int jf = 0; jf < 4; jf++) {
            int n = wc * 32 + jf * 8 + 2 * tig;
            #pragma unroll
            for (int hh = 0; hh < 2; hh++) {
                int rloc = wr * 64 + i * 16 + g + hh * 8;
                int r = row0 + rloc;
                float v0 = acc[i][jf][hh * 2 + 0] + fs[128 + n];
                float v1 = acc[i][jf][hh * 2 + 1] + fs[128 + n + 1];
                if (r < M) {
                    float2 hold = *(const float2*)(H + (size_t)r * 128 + n);
                    v0 += hold.x; v1 += hold.y;
                    if (MODE == 1) {
                        float2 st; st.x = v0; st.y = v1;
                        *(float2*)(H + (size_t)r * 128 + n) = st;
                    }
                }
                *(__half2*)&Asc[n >> 6][rloc * 72 + (n & 63)] = __floats2half2_rn(v0, v1);
            }
        }
    }
    // ---- GEMM3 ----
    ZERO_ACC(acc);
    for (int c = 0; c < 2; c++) {
        stage_W_h(Wnh, Ws, c, tid);
        __syncthreads();
        mma_chunk(Asc[c], Ws, acc, wr, wc, g, tig);
        __syncthreads();
    }
    if (MODE == 1) {
        #pragma unroll
        for (int i = 0; i < 4; i++) {
            #pragma unroll
            for (int jf = 0; jf < 4; jf++) {
                int n = wc * 32 + jf * 8 + 2 * tig;
                #pragma unroll
                for (int hh = 0; hh < 2; hh++) {
                    int r = row0 + wr * 64 + i * 16 + g + hh * 8;
                    if (r >= M) continue;
                    float v0 = acc[i][jf][hh * 2 + 0] + fs[256 + n];
                    float v1 = acc[i][jf][hh * 2 + 1] + fs[256 + n + 1];
                    *(__half2*)(HF + (size_t)r * 128 + n) = __floats2half2_rn(v0, v1);
                }
            }
        }
    } else {
        int np = nper ? __ldg(nper) : 5000;
        float ab2v = __ldg(ab2);
        #pragma unroll
        for (int i = 0; i < 4; i++) {
            #pragma unroll
            for (int hh = 0; hh < 2; hh++) {
                int rloc = wr * 64 + i * 16 + g + hh * 8;
                float s = 0.0f;
                #pragma unroll
                for (int jf = 0; jf < 4; jf++) {
                    int n = wc * 32 + jf * 8 + 2 * tig;
                    float v0 = sspf(acc[i][jf][hh * 2 + 0] + fs[256 + n]);
                    float v1 = sspf(acc[i][jf][hh * 2 + 1] + fs[256 + n + 1]);
                    s += v0 * fs[384 + n] + v1 * fs[384 + n + 1];
                }
                atomicAdd(&fs[512 + rloc], s);
            }
        }
        __syncthreads();
        if (tid < 128) {
            int r = row0 + tid;
            if (r < M) atomicAdd(&out[r / np], fs[512 + tid] + ab2v);
        }
    }
}

// ---------------- host ----------------
extern "C" void kernel_launch(void* const* d_in, const int* in_sizes, int n_in,
                              void* d_out, int out_size) {
    const int*   r   = (const int*)d_in[0];
    const float* xyz = (const float*)d_in[1];
    const int*   a   = (const int*)d_in[2];
    int base = 3;
    const int* nper = nullptr;
    if (n_in >= 19) { nper = (const int*)d_in[3]; base = 4; }
    const float* embed = (const float*)d_in[base + 0];
    const float* fw1   = (const float*)d_in[base + 1];
    const float* fb1   = (const float*)d_in[base + 2];
    const float* fw2   = (const float*)d_in[base + 3];
    const float* fb2   = (const float*)d_in[base + 4];
    const float* afw   = (const float*)d_in[base + 5];
    const float* afb   = (const float*)d_in[base + 6];
    const float* ow1   = (const float*)d_in[base + 7];
    const float* ob1   = (const float*)d_in[base + 8];
    const float* ow2   = (const float*)d_in[base + 9];
    const float* ob2   = (const float*)d_in[base + 10];
    const float* aw1   = (const float*)d_in[base + 11];
    const float* ab1   = (const float*)d_in[base + 12];
    const float* aw2   = (const float*)d_in[base + 13];
    const float* ab2   = (const float*)d_in[base + 14];
    float* out = (float*)d_out;

    float *ph, *pb1pad;
    __half *phf, *paggh, *ptbl, *pwhT, *pembedF;
    cudaGetSymbolAddress((void**)&ph,      g_h);
    cudaGetSymbolAddress((void**)&phf,     g_hf);
    cudaGetSymbolAddress((void**)&paggh,   g_aggh);
    cudaGetSymbolAddress((void**)&ptbl,    g_table);
    cudaGetSymbolAddress((void**)&pwhT,    g_whT);
    cudaGetSymbolAddress((void**)&pembedF, g_embedF);
    cudaGetSymbolAddress((void**)&pb1pad,  g_b1pad);

    const int FUSED_SMEM = 57856;
    cudaFuncSetAttribute(k_fused<1>, cudaFuncAttributeMaxDynamicSharedMemorySize, FUSED_SMEM);
    cudaFuncSetAttribute(k_fused<2>, cudaFuncAttributeMaxDynamicSharedMemorySize, FUSED_SMEM);
    cudaFuncSetAttribute(k_tbl, cudaFuncAttributeMaxDynamicSharedMemorySize, TBL_SMEM);

    k_init<<<(N_ATOMS * 32 + 255) / 256, 256>>>(r, embed, out, out_size);
    k_edges<<<(N_EDGES + 255) / 256, 256>>>(a, xyz);
    k_scan<<<1, 1024>>>();
    k_scatter<<<(N_EDGES + 255) / 256, 256>>>(a);
    k_prep<<<dim3(4, 4, 12), dim3(32, 8)>>>(ow1, ow2, afw, fw2);
    k_prepsmall<<<(3 * 128 * 32 + 128 * 128 + 255) / 256, 256>>>(fw1, aw1, ab1, aw2);
    k_tbl<<<3 * (TBL / 128), 256, TBL_SMEM>>>(fb1, fb2);

    // embedF = embed @ afw0 + afb0 (100 rows, one block), then hf0 = embedF[r]
    k_gemm<<<1, 256>>>(embed, pwhT + (size_t)6 * 16384, afb, pembedF, 100);
    k_hf0<<<(N_ATOMS * 16 + 255) / 256, 256>>>(r);

    int gemm_grid = (N_ATOMS + 127) / 128;
    for (int L = 0; L < 3; L++) {
        k_agg<<<N_ATOMS / 8, dim3(32, 8)>>>(ptbl + (size_t)L * TBL * 128);
        if (L < 2)
            k_fused<1><<<gemm_grid, 256, FUSED_SMEM>>>(
                paggh, pwhT + (size_t)L * 16384, ob1 + L * 128,
                pwhT + (size_t)(3 + L) * 16384, ob2 + L * 128, ph,
                pwhT + (size_t)(6 + L + 1) * 16384, afb + (L + 1) * 128, phf,
                nullptr, nullptr, nullptr, N_ATOMS);
        else
            k_fused<2><<<gemm_grid, 256, FUSED_SMEM>>>(
                paggh, pwhT + (size_t)L * 16384, ob1 + L * 128,
                pwhT + (size_t)(3 + L) * 16384, ob2 + L * 128, ph,
                pwhT + (size_t)12 * 16384, pb1pad, nullptr,
                ab2, out, nper, N_ATOMS);
    }
}

// round 15
// speedup vs baseline: 1.0742x; 1.0346x over previous
#include <cuda_runtime.h>
#include <cuda_fp16.h>
#include <math.h>

#define N_ATOMS 50000
#define N_EDGES 800000
#define TBL 4096
#define DMAXF 14.0f
#define LN2F 0.6931471805599453f

// ---------------- device scratch ----------------
__device__ float    g_h   [N_ATOMS * 128];
__device__ __half   g_hf  [N_ATOMS * 128];
__device__ __half   g_aggh[N_ATOMS * 128];
__device__ float    g_d   [N_EDGES];
__device__ unsigned g_metap[N_EDGES];        // src (17b) | table-index << 17
__device__ int      g_counts[N_ATOMS];
__device__ int      g_start [N_ATOMS];
__device__ int      g_cursor[N_ATOMS];
__device__ __half   g_table[3 * TBL * 128];
__device__ __half   g_whT  [13 * 128 * 128]; // [n][k]: 0-2 ow1, 3-5 ow2, 6-8 afw, 9-11 fw2, 12 w1pad
__device__ __half   g_w1T  [3 * 128 * 32];   // fw1 transposed [n=128][k=32]
__device__ __half   g_embedF[128 * 128];     // embed @ afw0 + afb0 (100 rows used)
__device__ float    g_b1pad[128];
__device__ float    g_aw2pad[128];

__device__ __forceinline__ float sspf(float x) {
    return fmaxf(x, 0.0f) + log1pf(expf(-fabsf(x))) - LN2F;
}

__device__ __forceinline__ void mma_f16(float* d, const unsigned* a, const unsigned* b) {
    asm volatile(
        "mma.sync.aligned.m16n8k16.row.col.f32.f16.f16.f32 "
        "{%0,%1,%2,%3}, {%4,%5,%6,%7}, {%8,%9}, {%0,%1,%2,%3};\n"
        : "+f"(d[0]), "+f"(d[1]), "+f"(d[2]), "+f"(d[3])
        : "r"(a[0]), "r"(a[1]), "r"(a[2]), "r"(a[3]), "r"(b[0]), "r"(b[1]));
}

// ---------------- init: zero counts + out ----------------
__global__ void k_init(float* __restrict__ out, int out_size) {
    int idx = blockIdx.x * blockDim.x + threadIdx.x;
    if (idx < N_ATOMS) g_counts[idx] = 0;
    if (idx < out_size) out[idx] = 0.0f;
}

// ---------------- edges ----------------
__global__ void k_edges(const int* __restrict__ a, const float* __restrict__ xyz) {
    int e = blockIdx.x * blockDim.x + threadIdx.x;
    if (e >= N_EDGES) return;
    int d0 = a[2 * e], s0 = a[2 * e + 1];
    float dx = xyz[3 * d0 + 0] - xyz[3 * s0 + 0];
    float dy = xyz[3 * d0 + 1] - xyz[3 * s0 + 1];
    float dz = xyz[3 * d0 + 2] - xyz[3 * s0 + 2];
    g_d[e] = sqrtf(dx * dx + dy * dy + dz * dz + 1e-12f);
    atomicAdd(&g_counts[d0], 1);
}

// ---------------- exclusive scan ----------------
__global__ __launch_bounds__(1024) void k_scan() {
    __shared__ int wsum[32];
    __shared__ int carry;
    __shared__ int tot;
    int t = threadIdx.x, lane = t & 31, w = t >> 5;
    if (t == 0) carry = 0;
    __syncthreads();
    for (int base = 0; base < N_ATOMS; base += 1024) {
        int i = base + t;
        int v = (i < N_ATOMS) ? g_counts[i] : 0;
        int incl = v;
        #pragma unroll
        for (int off = 1; off < 32; off <<= 1) {
            int x = __shfl_up_sync(0xffffffffu, incl, off);
            if (lane >= off) incl += x;
        }
        if (lane == 31) wsum[w] = incl;
        __syncthreads();
        if (w == 0) {
            int s = wsum[lane];
            int si = s;
            #pragma unroll
            for (int off = 1; off < 32; off <<= 1) {
                int x = __shfl_up_sync(0xffffffffu, si, off);
                if (lane >= off) si += x;
            }
            wsum[lane] = si - s;
            if (lane == 31) tot = si;
        }
        __syncthreads();
        int excl = carry + wsum[w] + incl - v;
        if (i < N_ATOMS) { g_start[i] = excl; g_cursor[i] = excl; }
        __syncthreads();
        if (t == 0) carry += tot;
        __syncthreads();
    }
}

// ---------------- scatter: pack (src | i0<<17) ----------------
__global__ void k_scatter(const int* __restrict__ a) {
    int e = blockIdx.x * blockDim.x + threadIdx.x;
    if (e >= N_EDGES) return;
    int d0 = a[2 * e];
    int pos = atomicAdd(&g_cursor[d0], 1);
    float d = g_d[e];
    float u = d * ((float)(TBL - 1) / DMAXF);
    int i0 = (int)(u + 0.5f);
    i0 = min(i0, TBL - 1);
    g_metap[pos] = (unsigned)a[2 * e + 1] | ((unsigned)i0 << 17);
}

// ---------------- weight transpose+convert: fp32 [k][n] -> half [n][k] ----------------
__global__ void k_prep(const float* __restrict__ ow1, const float* __restrict__ ow2,
                       const float* __restrict__ afw, const float* __restrict__ fw2) {
    __shared__ float t[32][33];
    int mat = blockIdx.z;
    const float* src = (mat < 3) ? ow1 + (size_t)mat * 16384
                     : (mat < 6) ? ow2 + (size_t)(mat - 3) * 16384
                     : (mat < 9) ? afw + (size_t)(mat - 6) * 16384
                                 : fw2 + (size_t)(mat - 9) * 16384;
    __half* dst = g_whT + (size_t)mat * 16384;
    int k0 = blockIdx.y * 32, n0 = blockIdx.x * 32;
    int tx = threadIdx.x, ty = threadIdx.y;   // (32, 8)
    #pragma unroll
    for (int q = 0; q < 4; q++)
        t[ty + q * 8][tx] = src[(size_t)(k0 + ty + q * 8) * 128 + n0 + tx];
    __syncthreads();
    #pragma unroll
    for (int q = 0; q < 4; q++)
        dst[(size_t)(n0 + ty + q * 8) * 128 + k0 + tx] = __float2half_rn(t[tx][ty + q * 8]);
}

// ---------------- small prep: fw1 transpose + readout pads (merged) ----------------
__global__ void k_prepsmall(const float* __restrict__ fw1, const float* __restrict__ aw1,
                            const float* __restrict__ ab1, const float* __restrict__ aw2) {
    int i = blockIdx.x * 256 + threadIdx.x;
    if (i < 3 * 128 * 32) {
        int L = i >> 12, rest = i & 4095, n = rest >> 5, k = rest & 31;
        g_w1T[i] = __float2half_rn(fw1[L * 4096 + k * 128 + n]);
    }
    int j = i - 3 * 128 * 32;
    if (j >= 0 && j < 128 * 128) {
        int n = j >> 7, k = j & 127;
        g_whT[12 * 16384 + j] = __float2half_rn((n < 64) ? aw1[k * 64 + n] : 0.0f);
    }
    if (j >= 0 && j < 128) {
        g_b1pad[j]  = (j < 64) ? ab1[j] : 0.0f;
        g_aw2pad[j] = (j < 64) ? aw2[j] : 0.0f;
    }
}

// ---------------- gather h = embed[r], hf0 = embedF[r] (merged) ----------------
__global__ void k_hfinit(const int* __restrict__ r, const float* __restrict__ embed) {
    int idx = blockIdx.x * 256 + threadIdx.x;
    if (idx >= N_ATOMS * 32) return;
    int atom = idx >> 5, j = idx & 31;
    int ri = r[atom];
    ((float4*)g_h)[atom * 32 + j] = ((const float4*)embed)[(size_t)ri * 32 + j];
    if (j < 16)
        ((uint4*)g_hf)[atom * 16 + j] = ((const uint4*)g_embedF)[(size_t)ri * 16 + j];
}

// ================= GEMM building blocks =================
__device__ __forceinline__ void stage_A_f(const float* __restrict__ A, __half* As,
                                          int row0, int c, int M, int tid) {
    int ar = tid >> 1;
    int k0 = (tid & 1) * 32;
    const float* ap = A + (size_t)(row0 + ar) * 128 + c * 64 + k0;
    bool valid = (row0 + ar) < M;
    #pragma unroll
    for (int p = 0; p < 8; p++) {
        float4 v = make_float4(0.f, 0.f, 0.f, 0.f);
        if (valid) v = *(const float4*)(ap + p * 4);
        *(__half2*)&As[ar * 72 + k0 + p * 4]     = __floats2half2_rn(v.x, v.y);
        *(__half2*)&As[ar * 72 + k0 + p * 4 + 2] = __floats2half2_rn(v.z, v.w);
    }
}

// stage half A [m][128] -> As0/As1 (both chunks) in one pass
__device__ __forceinline__ void stage_A_h2(const __half* __restrict__ Ah, __half* As0,
                                           __half* As1, int row0, int M, int tid) {
    #pragma unroll
    for (int p = 0; p < 8; p++) {
        int idx = tid + p * 256;          // 0..2047
        int m = idx >> 4;                 // 0..127
        int k8 = (idx & 15) * 8;          // 0..120
        uint4 v = make_uint4(0, 0, 0, 0);
        if (row0 + m < M) v = *(const uint4*)(Ah + (size_t)(row0 + m) * 128 + k8);
        __half* dst = (k8 < 64) ? As0 : As1;
        *(uint4*)&dst[m * 72 + (k8 & 63)] = v;
    }
}

// stage W half [n][128] -> Wsf full [n][k] stride 136
__device__ __forceinline__ void stage_W_full(const __half* __restrict__ Wh, __half* Wsf, int tid) {
    #pragma unroll
    for (int p = 0; p < 8; p++) {
        int idx = tid + p * 256;          // 0..2047
        int n = idx >> 4;                 // 0..127
        int k8 = (idx & 15) * 8;
        *(uint4*)&Wsf[n * 136 + k8] = *(const uint4*)(Wh + (size_t)n * 128 + k8);
    }
}

// stage W 64-chunk (for k_gemm/k_tbl, stride 72)
__device__ __forceinline__ void stage_W_h(const __half* __restrict__ Wh, __half* Ws,
                                          int c, int tid) {
    #pragma unroll
    for (int p = 0; p < 4; p++) {
        int idx = tid + p * 256;
        int n = idx >> 3, k8 = (idx & 7) * 8;
        *(uint4*)&Ws[n * 72 + k8] = *(const uint4*)(Wh + (size_t)n * 128 + c * 64 + k8);
    }
}

// mma over one 64-k chunk: As stride 72, W from Wsf stride 136 at offset c*64
__device__ __forceinline__ void mma_chunkW(const __half* As, const __half* Wsf, int c,
                                           float acc[4][4][4], int wr, int wc, int g, int tig) {
    #pragma unroll
    for (int ks = 0; ks < 64; ks += 16) {
        unsigned af[4][4], bf[4][2];
        #pragma unroll
        for (int i = 0; i < 4; i++) {
            int r = wr * 64 + i * 16 + g;
            af[i][0] = *(const unsigned*)&As[r * 72 + ks + tig * 2];
            af[i][1] = *(const unsigned*)&As[(r + 8) * 72 + ks + tig * 2];
            af[i][2] = *(const unsigned*)&As[r * 72 + ks + tig * 2 + 8];
            af[i][3] = *(const unsigned*)&As[(r + 8) * 72 + ks + tig * 2 + 8];
        }
        #pragma unroll
        for (int jf = 0; jf < 4; jf++) {
            int n = wc * 32 + jf * 8 + g;
            bf[jf][0] = *(const unsigned*)&Wsf[n * 136 + c * 64 + ks + tig * 2];
            bf[jf][1] = *(const unsigned*)&Wsf[n * 136 + c * 64 + ks + tig * 2 + 8];
        }
        #pragma unroll
        for (int i = 0; i < 4; i++)
            #pragma unroll
            for (int jf = 0; jf < 4; jf++)
                mma_f16(acc[i][jf], af[i], bf[jf]);
    }
}

// mma with both operands stride-72 chunks (k_gemm, k_tbl)
__device__ __forceinline__ void mma_chunk(const __half* As, const __half* Ws,
                                          float acc[4][4][4], int wr, int wc, int g, int tig) {
    #pragma unroll
    for (int ks = 0; ks < 64; ks += 16) {
        unsigned af[4][4], bf[4][2];
        #pragma unroll
        for (int i = 0; i < 4; i++) {
            int r = wr * 64 + i * 16 + g;
            af[i][0] = *(const unsigned*)&As[r * 72 + ks + tig * 2];
            af[i][1] = *(const unsigned*)&As[(r + 8) * 72 + ks + tig * 2];
            af[i][2] = *(const unsigned*)&As[r * 72 + ks + tig * 2 + 8];
            af[i][3] = *(const unsigned*)&As[(r + 8) * 72 + ks + tig * 2 + 8];
        }
        #pragma unroll
        for (int jf = 0; jf < 4; jf++) {
            int n = wc * 32 + jf * 8 + g;
            bf[jf][0] = *(const unsigned*)&Ws[n * 72 + ks + tig * 2];
            bf[jf][1] = *(const unsigned*)&Ws[n * 72 + ks + tig * 2 + 8];
        }
        #pragma unroll
        for (int i = 0; i < 4; i++)
            #pragma unroll
            for (int jf = 0; jf < 4; jf++)
                mma_f16(acc[i][jf], af[i], bf[jf]);
    }
}

#define ZERO_ACC(acc) { _Pragma("unroll") for (int i = 0; i < 4; i++) _Pragma("unroll") \
    for (int jf = 0; jf < 4; jf++) _Pragma("unroll") for (int q = 0; q < 4; q++) acc[i][jf][q] = 0.0f; }

// ---------------- fused table build (dynamic smem; Ts stride 136) ----------------
#define TBL_SMEM (128 * 40 * 2 + 128 * 136 * 2 + 128 * 72 * 2 + 512 + 512)
__global__ __launch_bounds__(256) void k_tbl(const float* __restrict__ fb1,
                                             const float* __restrict__ fb2) {
    extern __shared__ char dsm[];
    __half* Gs = (__half*)dsm;                          // [m][k=32] stride 40
    __half* Ts = (__half*)(dsm + 10240);                // [m][k=128] stride 136
    __half* Ws = (__half*)(dsm + 10240 + 34816);        // [n][k] stride 72 (or 40 in GEMM1)
    float* bs1 = (float*)(dsm + 10240 + 34816 + 18432);
    float* bs2 = (float*)(dsm + 10240 + 34816 + 18432 + 512);
    int tid = threadIdx.x;
    int lane = tid & 31, wid = tid >> 5;
    int wr = wid >> 2, wc = wid & 3;
    int g = lane >> 2, tig = lane & 3;
    int L = blockIdx.x / (TBL / 128);
    int e0 = (blockIdx.x % (TBL / 128)) * 128;
    float width = 5.0f / 31.0f;
    float coeff = -0.5f / (width * width);
    for (int i = tid; i < 128 * 32; i += 256) {
        int m = i >> 5, k = i & 31;
        float d = (float)(e0 + m) * (DMAXF / (float)(TBL - 1));
        float x = d - (float)k * width;
        Gs[m * 40 + k] = __float2half_rn(expf(coeff * x * x));
    }
    if (tid < 128) { bs1[tid] = fb1[L * 128 + tid]; bs2[tid] = fb2[L * 128 + tid]; }
    for (int i = tid; i < 128 * 4; i += 256) {
        int n = i >> 2, k8 = (i & 3) * 8;
        *(uint4*)&Ws[n * 40 + k8] = *(const uint4*)&g_w1T[(size_t)(L * 128 + n) * 32 + k8];
    }
    __syncthreads();
    float acc[4][4][4];
    ZERO_ACC(acc);
    #pragma unroll
    for (int ks = 0; ks < 32; ks += 16) {
        unsigned af[4][4], bf[4][2];
        #pragma unroll
        for (int i = 0; i < 4; i++) {
            int r = wr * 64 + i * 16 + g;
            af[i][0] = *(const unsigned*)&Gs[r * 40 + ks + tig * 2];
            af[i][1] = *(const unsigned*)&Gs[(r + 8) * 40 + ks + tig * 2];
            af[i][2] = *(const unsigned*)&Gs[r * 40 + ks + tig * 2 + 8];
            af[i][3] = *(const unsigned*)&Gs[(r + 8) * 40 + ks + tig * 2 + 8];
        }
        #pragma unroll
        for (int jf = 0; jf < 4; jf++) {
            int n = wc * 32 + jf * 8 + g;
            bf[jf][0] = *(const unsigned*)&Ws[n * 40 + ks + tig * 2];
            bf[jf][1] = *(const unsigned*)&Ws[n * 40 + ks + tig * 2 + 8];
        }
        #pragma unroll
        for (int i = 0; i < 4; i++)
            #pragma unroll
            for (int jf = 0; jf < 4; jf++)
                mma_f16(acc[i][jf], af[i], bf[jf]);
    }
    #pragma unroll
    for (int i = 0; i < 4; i++) {
        #pragma unroll
        for (int jf = 0; jf < 4; jf++) {
            int n = wc * 32 + jf * 8 + 2 * tig;
            #pragma unroll
            for (int hh = 0; hh < 2; hh++) {
                int rloc = wr * 64 + i * 16 + g + hh * 8;
                float v0 = sspf(acc[i][jf][hh * 2 + 0] + bs1[n]);
                float v1 = sspf(acc[i][jf][hh * 2 + 1] + bs1[n + 1]);
                *(__half2*)&Ts[rloc * 136 + n] = __floats2half2_rn(v0, v1);
            }
        }
    }
    ZERO_ACC(acc);
    const __half* w2T = g_whT + (size_t)(9 + L) * 16384;
    for (int c = 0; c < 2; c++) {
        __syncthreads();
        stage_W_h(w2T, Ws, c, tid);
        __syncthreads();
        #pragma unroll
        for (int ks = 0; ks < 64; ks += 16) {
            unsigned af[4][4], bf[4][2];
            #pragma unroll
            for (int i = 0; i < 4; i++) {
                int r = wr * 64 + i * 16 + g;
                af[i][0] = *(const unsigned*)&Ts[r * 136 + c * 64 + ks + tig * 2];
                af[i][1] = *(const unsigned*)&Ts[(r + 8) * 136 + c * 64 + ks + tig * 2];
                af[i][2] = *(const unsigned*)&Ts[r * 136 + c * 64 + ks + tig * 2 + 8];
                af[i][3] = *(const unsigned*)&Ts[(r + 8) * 136 + c * 64 + ks + tig * 2 + 8];
            }
            #pragma unroll
            for (int jf = 0; jf < 4; jf++) {
                int n = wc * 32 + jf * 8 + g;
                bf[jf][0] = *(const unsigned*)&Ws[n * 72 + ks + tig * 2];
                bf[jf][1] = *(const unsigned*)&Ws[n * 72 + ks + tig * 2 + 8];
            }
            #pragma unroll
            for (int i = 0; i < 4; i++)
                #pragma unroll
                for (int jf = 0; jf < 4; jf++)
                    mma_f16(acc[i][jf], af[i], bf[jf]);
        }
    }
    __half* trow = g_table + ((size_t)L * TBL + e0) * 128;
    #pragma unroll
    for (int i = 0; i < 4; i++) {
        #pragma unroll
        for (int jf = 0; jf < 4; jf++) {
            int n = wc * 32 + jf * 8 + 2 * tig;
            #pragma unroll
            for (int hh = 0; hh < 2; hh++) {
                int rloc = wr * 64 + i * 16 + g + hh * 8;
                float v0 = acc[i][jf][hh * 2 + 0] + bs2[n];
                float v1 = acc[i][jf][hh * 2 + 1] + bs2[n + 1];
                *(__half2*)&trow[(size_t)rloc * 128 + n] = __floats2half2_rn(v0, v1);
            }
        }
    }
}

// ---------------- aggregation: 2 edges/iter, 16B lanes, warp per atom ----------------
__global__ __launch_bounds__(256) void k_agg(const __half* __restrict__ tbl) {
    int atom = blockIdx.x * 8 + threadIdx.y;
    int lane = threadIdx.x;
    int hid = lane >> 4;               // 0: even edges, 1: odd edges
    int fl = lane & 15;                // features 8*fl .. 8*fl+7
    int s = g_start[atom], c = g_counts[atom];
    float acc[8];
    #pragma unroll
    for (int q = 0; q < 8; q++) acc[q] = 0.0f;
    const uint4* t4 = (const uint4*)tbl;
    const uint4* h4 = (const uint4*)g_hf;
    #pragma unroll 2
    for (int e = hid; e < c; e += 2) {
        unsigned m = __ldg(&g_metap[s + e]);
        int src = m & 0x1FFFF;
        int i0 = m >> 17;
        uint4 wv = __ldg(&t4[(size_t)i0 * 16 + fl]);
        uint4 hv = __ldg(&h4[(size_t)src * 16 + fl]);
        const __half2* wp = (const __half2*)&wv;
        const __half2* hp = (const __half2*)&hv;
        #pragma unroll
        for (int q = 0; q < 4; q++) {
            float2 wf = __half22float2(wp[q]);
            float2 hf = __half22float2(hp[q]);
            acc[2 * q]     = fmaf(hf.x, wf.x, acc[2 * q]);
            acc[2 * q + 1] = fmaf(hf.y, wf.y, acc[2 * q + 1]);
        }
    }
    #pragma unroll
    for (int q = 0; q < 8; q++) acc[q] += __shfl_down_sync(0xffffffffu, acc[q], 16);
    if (hid == 0) {
        uint4 st;
        __half2* sp = (__half2*)&st;
        #pragma unroll
        for (int q = 0; q < 4; q++) sp[q] = __floats2half2_rn(acc[2 * q], acc[2 * q + 1]);
        ((uint4*)g_aggh)[(size_t)atom * 16 + fl] = st;
    }
}

// ---------------- generic GEMM: fp32-A, half-W -> half out (embedF only) ----------------
__global__ __launch_bounds__(256) void k_gemm(const float* __restrict__ A,
                                              const __half* __restrict__ Wh,
                                              const float* __restrict__ bias,
                                              __half* __restrict__ Ch, int M) {
    __shared__ __half As[128 * 72];
    __shared__ __half Ws[128 * 72];
    __shared__ float bs[128];
    int tid = threadIdx.x;
    int lane = tid & 31, wid = tid >> 5;
    int wr = wid >> 2, wc = wid & 3;
    int g = lane >> 2, tig = lane & 3;
    int row0 = blockIdx.x * 128;
    float acc[4][4][4];
    ZERO_ACC(acc);
    if (tid < 128) bs[tid] = bias[tid];

    for (int c = 0; c < 2; c++) {
        stage_A_f(A, As, row0, c, M, tid);
        stage_W_h(Wh, Ws, c, tid);
        __syncthreads();
        mma_chunk(As, Ws, acc, wr, wc, g, tig);
        __syncthreads();
    }
    #pragma unroll
    for (int i = 0; i < 4; i++) {
        int rbase = row0 + wr * 64 + i * 16 + g;
        #pragma unroll
        for (int jf = 0; jf < 4; jf++) {
            int n = wc * 32 + jf * 8 + 2 * tig;
            #pragma unroll
            for (int hh = 0; hh < 2; hh++) {
                int r = rbase + hh * 8;
                if (r >= M) continue;
                float v0 = acc[i][jf][hh * 2 + 0] + bs[n];
                float v1 = acc[i][jf][hh * 2 + 1] + bs[n + 1];
                *(__half2*)(Ch + (size_t)r * 128 + n) = __floats2half2_rn(v0, v1);
            }
        }
    }
}

// ---------------- fused layer: full-W staging, 5 syncs ----------------
// MODE 1: GEMM3 = h@Wn+bn -> HF ; MODE 2: fused readout
#define FUSED_SMEM (18432 + 18432 + 34816 + 2560)
template <int MODE>
__global__ __launch_bounds__(256) void k_fused(const __half* __restrict__ Ah,
                                               const __half* __restrict__ W1h,
                                               const float* __restrict__ b1,
                                               const __half* __restrict__ W2h,
                                               const float* __restrict__ b2,
                                               float* __restrict__ H,
                                               const __half* __restrict__ Wnh,
                                               const float* __restrict__ bn,
                                               __half* __restrict__ HF,
                                               const float* __restrict__ ab2,
                                               float* __restrict__ out,
                                               const int* __restrict__ nper, int M) {
    extern __shared__ char dsm[];
    __half* As0 = (__half*)dsm;
    __half* As1 = (__half*)(dsm + 18432);
    __half* Wsf = (__half*)(dsm + 36864);              // [n=128][k=128] stride 136
    float*  fs  = (float*)(dsm + 36864 + 34816);       // b1 | b2 | bn | aw2 | srow
    __half* Asc[2] = {As0, As1};
    int tid = threadIdx.x;
    int lane = tid & 31, wid = tid >> 5;
    int wr = wid >> 2, wc = wid & 3;
    int g = lane >> 2, tig = lane & 3;
    int row0 = blockIdx.x * 128;
    if (tid < 128) {
        fs[tid] = b1[tid];
        fs[128 + tid] = b2[tid];
        fs[256 + tid] = bn[tid];
        if (MODE == 2) { fs[384 + tid] = g_aw2pad[tid]; fs[512 + tid] = 0.0f; }
    }

    // ---- GEMM1: t1 = ssp(agg @ W1 + b1) ----
    float acc[4][4][4];
    ZERO_ACC(acc);
    stage_A_h2(Ah, As0, As1, row0, M, tid);
    stage_W_full(W1h, Wsf, tid);
    __syncthreads();                                   // S1
    mma_chunkW(As0, Wsf, 0, acc, wr, wc, g, tig);
    mma_chunkW(As1, Wsf, 1, acc, wr, wc, g, tig);
    __syncthreads();                                   // S2 (As/Wsf reads done)
    #pragma unroll
    for (int i = 0; i < 4; i++) {
        #pragma unroll
        for (int jf = 0; jf < 4; jf++) {
            int n = wc * 32 + jf * 8 + 2 * tig;
            #pragma unroll
            for (int hh = 0; hh < 2; hh++) {
                int rloc = wr * 64 + i * 16 + g + hh * 8;
                float v0 = sspf(acc[i][jf][hh * 2 + 0] + fs[n]);
                float v1 = sspf(acc[i][jf][hh * 2 + 1] + fs[n + 1]);
                *(__half2*)&Asc[n >> 6][rloc * 72 + (n & 63)] = __floats2half2_rn(v0, v1);
            }
        }
    }
    // ---- GEMM2: h_new = h + t1 @ W2 + b2 ----
    ZERO_ACC(acc);
    stage_W_full(W2h, Wsf, tid);
    __syncthreads();                                   // S3 (epi1 As + W2 visible)
    mma_chunkW(As0, Wsf, 0, acc, wr, wc, g, tig);
    mma_chunkW(As1, Wsf, 1, acc, wr, wc, g, tig);
    __syncthreads();                                   // S4
    #pragma unroll
    for (int i = 0; i < 4; i++) {
        #pragma unroll
        for (int jf = 0; jf < 4; jf++) {
            int n = wc * 32 + jf * 8 + 2 * tig;
            #pragma unroll
            for (int hh = 0; hh < 2; hh++) {
                int rloc = wr * 64 + i * 16 + g + hh * 8;
                int r = row0 + rloc;
                float v0 = acc[i][jf][hh * 2 + 0] + fs[128 + n];
                float v1 = acc[i][jf][hh * 2 + 1] + fs[128 + n + 1];
                if (r < M) {
                    float2 hold = *(const float2*)(H + (size_t)r * 128 + n);
                    v0 += hold.x; v1 += hold.y;
                    if (MODE == 1) {
                        float2 st; st.x = v0; st.y = v1;
                        *(float2*)(H + (size_t)r * 128 + n) = st;
                    }
                }
                *(__half2*)&Asc[n >> 6][rloc * 72 + (n & 63)] = __floats2half2_rn(v0, v1);
            }
        }
    }
    // ---- GEMM3 ----
    ZERO_ACC(acc);
    stage_W_full(Wnh, Wsf, tid);
    __syncthreads();                                   // S5
    mma_chunkW(As0, Wsf, 0, acc, wr, wc, g, tig);
    mma_chunkW(As1, Wsf, 1, acc, wr, wc, g, tig);
    if (MODE == 1) {
        #pragma unroll
        for (int i = 0; i < 4; i++) {
            #pragma unroll
            for (int jf = 0; jf < 4; jf++) {
                int n = wc * 32 + jf * 8 + 2 * tig;
                #pragma unroll
                for (int hh = 0; hh < 2; hh++) {
                    int r = row0 + wr * 64 + i * 16 + g + hh * 8;
                    if (r >= M) continue;
                    float v0 = acc[i][jf][hh * 2 + 0] + fs[256 + n];
                    float v1 = acc[i][jf][hh * 2 + 1] + fs[256 + n + 1];
                    *(__half2*)(HF + (size_t)r * 128 + n) = __floats2half2_rn(v0, v1);
                }
            }
        }
    } else {
        int np = nper ? __ldg(nper) : 5000;
        float ab2v = __ldg(ab2);
        #pragma unroll
        for (int i = 0; i < 4; i++) {
            #pragma unroll
            for (int hh = 0; hh < 2; hh++) {
                int rloc = wr * 64 + i * 16 + g + hh * 8;
                float s = 0.0f;
                #pragma unroll
                for (int jf = 0; jf < 4; jf++) {
                    int n = wc * 32 + jf * 8 + 2 * tig;
                    float v0 = sspf(acc[i][jf][hh * 2 + 0] + fs[256 + n]);
                    float v1 = sspf(acc[i][jf][hh * 2 + 1] + fs[256 + n + 1]);
                    s += v0 * fs[384 + n] + v1 * fs[384 + n + 1];
                }
                atomicAdd(&fs[512 + rloc], s);
            }
        }
        __syncthreads();
        if (tid < 128) {
            int r = row0 + tid;
            if (r < M) atomicAdd(&out[r / np], fs[512 + tid] + ab2v);
        }
    }
}

// ---------------- host ----------------
extern "C" void kernel_launch(void* const* d_in, const int* in_sizes, int n_in,
                              void* d_out, int out_size) {
    const int*   r   = (const int*)d_in[0];
    const float* xyz = (const float*)d_in[1];
    const int*   a   = (const int*)d_in[2];
    int base = 3;
    const int* nper = nullptr;
    if (n_in >= 19) { nper = (const int*)d_in[3]; base = 4; }
    const float* embed = (const float*)d_in[base + 0];
    const float* fw1   = (const float*)d_in[base + 1];
    const float* fb1   = (const float*)d_in[base + 2];
    const float* fw2   = (const float*)d_in[base + 3];
    const float* fb2   = (const float*)d_in[base + 4];
    const float* afw   = (const float*)d_in[base + 5];
    const float* afb   = (const float*)d_in[base + 6];
    const float* ow1   = (const float*)d_in[base + 7];
    const float* ob1   = (const float*)d_in[base + 8];
    const float* ow2   = (const float*)d_in[base + 9];
    const float* ob2   = (const float*)d_in[base + 10];
    const float* aw1   = (const float*)d_in[base + 11];
    const float* ab1   = (const float*)d_in[base + 12];
    const float* aw2   = (const float*)d_in[base + 13];
    const float* ab2   = (const float*)d_in[base + 14];
    float* out = (float*)d_out;

    float *ph, *pb1pad;
    __half *phf, *paggh, *ptbl, *pwhT, *pembedF;
    cudaGetSymbolAddress((void**)&ph,      g_h);
    cudaGetSymbolAddress((void**)&phf,     g_hf);
    cudaGetSymbolAddress((void**)&paggh,   g_aggh);
    cudaGetSymbolAddress((void**)&ptbl,    g_table);
    cudaGetSymbolAddress((void**)&pwhT,    g_whT);
    cudaGetSymbolAddress((void**)&pembedF, g_embedF);
    cudaGetSymbolAddress((void**)&pb1pad,  g_b1pad);

    cudaFuncSetAttribute(k_fused<1>, cudaFuncAttributeMaxDynamicSharedMemorySize, FUSED_SMEM);
    cudaFuncSetAttribute(k_fused<2>, cudaFuncAttributeMaxDynamicSharedMemorySize, FUSED_SMEM);
    cudaFuncSetAttribute(k_tbl, cudaFuncAttributeMaxDynamicSharedMemorySize, TBL_SMEM);

    k_init<<<(N_ATOMS + 255) / 256, 256>>>(out, out_size);
    k_edges<<<(N_EDGES + 255) / 256, 256>>>(a, xyz);
    k_scan<<<1, 1024>>>();
    k_scatter<<<(N_EDGES + 255) / 256, 256>>>(a);
    k_prep<<<dim3(4, 4, 12), dim3(32, 8)>>>(ow1, ow2, afw, fw2);
    k_prepsmall<<<(3 * 128 * 32 + 128 * 128 + 255) / 256, 256>>>(fw1, aw1, ab1, aw2);
    k_tbl<<<3 * (TBL / 128), 256, TBL_SMEM>>>(fb1, fb2);

    // embedF = embed @ afw0 + afb0 (100 rows), then h = embed[r], hf0 = embedF[r]
    k_gemm<<<1, 256>>>(embed, pwhT + (size_t)6 * 16384, afb, pembedF, 100);
    k_hfinit<<<(N_ATOMS * 32 + 255) / 256, 256>>>(r, embed);

    int gemm_grid = (N_ATOMS + 127) / 128;
    for (int L = 0; L < 3; L++) {
        k_agg<<<N_ATOMS / 8, dim3(32, 8)>>>(ptbl + (size_t)L * TBL * 128);
        if (L < 2)
            k_fused<1><<<gemm_grid, 256, FUSED_SMEM>>>(
                paggh, pwhT + (size_t)L * 16384, ob1 + L * 128,
                pwhT + (size_t)(3 + L) * 16384, ob2 + L * 128, ph,
                pwhT + (size_t)(6 + L + 1) * 16384, afb + (L + 1) * 128, phf,
                nullptr, nullptr, nullptr, N_ATOMS);
        else
            k_fused<2><<<gemm_grid, 256, FUSED_SMEM>>>(
                paggh, pwhT + (size_t)L * 16384, ob1 + L * 128,
                pwhT + (size_t)(3 + L) * 16384, ob2 + L * 128, ph,
                pwhT + (size_t)12 * 16384, pb1pad, nullptr,
                ab2, out, nper, N_ATOMS);
    }
}